// round 1
// baseline (speedup 1.0000x reference)
#include <cuda_runtime.h>
#include <math.h>

#define B 64
#define C 32
#define D 256
#define F (C * D)          // 8192
#define BC (B * C)         // 2048
#define TEMP 0.1f
#define EPS 1e-8f

// ---------------- scratch (no allocations allowed) ----------------
__device__ float g_rn2_is[BC];     // per-row squared norms of children_is
__device__ float g_rn2_js[BC];     // per-row squared norms of children_js
__device__ float g_pos[B];         // positive logits
__device__ float g_sims[B][2 * B]; // [i][0..B) = sim_j, [i][B..2B) = sim_k

// ---------------- kernel 1: per-row squared norms ----------------
// 2*B*C = 4096 rows of 256 floats; one warp per row.
__global__ void rownorm_kernel(const float* __restrict__ is_,
                               const float* __restrict__ js_) {
    int gw   = (blockIdx.x * blockDim.x + threadIdx.x) >> 5;
    int lane = threadIdx.x & 31;
    if (gw >= 2 * BC) return;
    int r = gw & (BC - 1);
    const float* base = (gw < BC) ? is_ : js_;
    const float4* row = (const float4*)(base + (size_t)r * D);
    float4 v0 = row[lane];
    float4 v1 = row[lane + 32];
    float s = v0.x * v0.x + v0.y * v0.y + v0.z * v0.z + v0.w * v0.w
            + v1.x * v1.x + v1.y * v1.y + v1.z * v1.z + v1.w * v1.w;
#pragma unroll
    for (int o = 16; o; o >>= 1) s += __shfl_xor_sync(0xffffffffu, s, o);
    if (lane == 0) {
        float* dst = (gw < BC) ? g_rn2_is : g_rn2_js;
        dst[r] = s;
    }
}

// ---------------- kernel 2: positive logits ----------------
// one CTA (256 thr) per anchor i: dot(flat_i[i], flat_j[i]) over 8192.
__global__ void pos_kernel(const float* __restrict__ is_,
                           const float* __restrict__ js_) {
    int i = blockIdx.x, tid = threadIdx.x;
    const float4* a  = (const float4*)(is_ + (size_t)i * F);
    const float4* b4 = (const float4*)(js_ + (size_t)i * F);
    float d = 0.f;
    for (int t = tid; t < F / 4; t += 256) {
        float4 x = a[t], y = b4[t];
        d += x.x * y.x + x.y * y.y + x.z * y.z + x.w * y.w;
    }
    __shared__ float sr[8];
#pragma unroll
    for (int o = 16; o; o >>= 1) d += __shfl_xor_sync(0xffffffffu, d, o);
    if ((tid & 31) == 0) sr[tid >> 5] = d;
    __syncthreads();
    if (tid == 0) {
        float dot = 0.f;
#pragma unroll
        for (int k = 0; k < 8; k++) dot += sr[k];
        float na2 = 0.f, nb2 = 0.f;
#pragma unroll
        for (int c = 0; c < C; c++) {
            na2 += g_rn2_is[i * C + c];
            nb2 += g_rn2_js[i * C + c];
        }
        g_pos[i] = dot / fmaxf(sqrtf(na2) * sqrtf(nb2), EPS) / TEMP;
    }
}

// ---------------- kernel 3: gathered negative similarities ----------------
// grid = dim3(8, B): blockIdx.y = anchor i, blockIdx.x = jb-group of 8.
// 256 threads, warp w handles jb = part*8 + w for BOTH matrices (j then k).
__global__ void sims_kernel(const float* __restrict__ is_,
                            const float* __restrict__ js_,
                            const int* __restrict__ idxj,
                            const int* __restrict__ idxk) {
    __shared__ float s_anchor[F];   // 32 KB: flat_i[i]
    __shared__ float s_na;
    int i    = blockIdx.y;
    int part = blockIdx.x;
    int tid  = threadIdx.x, lane = tid & 31, w = tid >> 5;

    const float4* src = (const float4*)(is_ + (size_t)i * F);
    float4* dst4 = (float4*)s_anchor;
    for (int t = tid; t < F / 4; t += 256) dst4[t] = src[t];
    if (tid == 0) {
        float na2 = 0.f;
#pragma unroll
        for (int c = 0; c < C; c++) na2 += g_rn2_is[i * C + c];
        s_na = sqrtf(na2);
    }
    __syncthreads();
    float na = s_na;
    int  jb  = part * 8 + w;

#pragma unroll
    for (int m = 0; m < 2; m++) {
        float sim;
        if (jb == i) {
            sim = -INFINITY;
        } else {
            const float* basev = (m == 0) ? js_ : is_;
            const float* rn2   = (m == 0) ? g_rn2_js : g_rn2_is;
            const int*   idx   = ((m == 0) ? idxj : idxk) + ((size_t)i * B + jb) * C;
            float acc0 = 0.f, acc1 = 0.f, acc2 = 0.f, acc3 = 0.f;
            float acc4 = 0.f, acc5 = 0.f, acc6 = 0.f, acc7 = 0.f;
            float n2 = 0.f;   // identical across lanes (idx is lane-uniform)
#pragma unroll 4
            for (int c = 0; c < C; c++) {
                int r = idx[c];
                n2 += rn2[jb * C + r];
                const float4* row = (const float4*)(basev + ((size_t)(jb * C + r)) * D);
                const float4* anc = (const float4*)(s_anchor + c * D);
                float4 b0 = row[lane];
                float4 b1 = row[lane + 32];
                float4 a0 = anc[lane];
                float4 a1 = anc[lane + 32];
                acc0 += a0.x * b0.x; acc1 += a0.y * b0.y;
                acc2 += a0.z * b0.z; acc3 += a0.w * b0.w;
                acc4 += a1.x * b1.x; acc5 += a1.y * b1.y;
                acc6 += a1.z * b1.z; acc7 += a1.w * b1.w;
            }
            float dot = ((acc0 + acc1) + (acc2 + acc3))
                      + ((acc4 + acc5) + (acc6 + acc7));
#pragma unroll
            for (int o = 16; o; o >>= 1) dot += __shfl_xor_sync(0xffffffffu, dot, o);
            sim = dot / fmaxf(na * sqrtf(n2), EPS) / TEMP;
        }
        if (lane == 0) g_sims[i][m * B + jb] = sim;
    }
}

// ---------------- kernel 4: logsumexp + final reduction ----------------
// 1 block, 256 threads; warp w handles anchors w*8 .. w*8+7.
__global__ void final_kernel(float* __restrict__ out) {
    int lane = threadIdx.x & 31, w = threadIdx.x >> 5;
    float acc = 0.f;
    for (int ii = 0; ii < 8; ii++) {
        int i = w * 8 + ii;
        float pos = g_pos[i];
        float mx = pos;
        for (int t = lane; t < 2 * B; t += 32) mx = fmaxf(mx, g_sims[i][t]);
#pragma unroll
        for (int o = 16; o; o >>= 1) mx = fmaxf(mx, __shfl_xor_sync(0xffffffffu, mx, o));
        float s = (lane == 0) ? expf(pos - mx) : 0.f;
        for (int t = lane; t < 2 * B; t += 32) {
            float v = g_sims[i][t];
            s += expf(v - mx);   // exp(-inf - mx) == 0 handles the diagonal
        }
#pragma unroll
        for (int o = 16; o; o >>= 1) s += __shfl_xor_sync(0xffffffffu, s, o);
        float lse = logf(s) + mx;
        acc += lse - pos;        // identical across lanes post-reduction
    }
    __shared__ float sred[8];
    if (lane == 0) sred[w] = acc;
    __syncthreads();
    if (threadIdx.x == 0) {
        float t = 0.f;
#pragma unroll
        for (int k = 0; k < 8; k++) t += sred[k];
        out[0] = t / (2.0f * B);
    }
}

// ---------------- launch ----------------
extern "C" void kernel_launch(void* const* d_in, const int* in_sizes, int n_in,
                              void* d_out, int out_size) {
    const float* is_  = (const float*)d_in[0];   // children_is [B,C,D] f32
    const float* js_  = (const float*)d_in[1];   // children_js [B,C,D] f32
    const int*   idxj = (const int*)d_in[2];     // neg_idx_j  [B,B,C] i32
    const int*   idxk = (const int*)d_in[3];     // neg_idx_k  [B,B,C] i32
    // d_in[4] = partnet_ids (unused)
    float* out = (float*)d_out;

    rownorm_kernel<<<(2 * BC) / 8, 256>>>(is_, js_);   // 512 blocks, 1 warp/row
    pos_kernel<<<B, 256>>>(is_, js_);
    sims_kernel<<<dim3(8, B), 256>>>(is_, js_, idxj, idxk);
    final_kernel<<<1, 256>>>(out);
}

// round 4
// speedup vs baseline: 1.4398x; 1.4398x over previous
#include <cuda_runtime.h>
#include <math.h>

#define B 64
#define C 32
#define D 256
#define F (C * D)          // 8192
#define BC (B * C)         // 2048
#define TEMP 0.1f
#define EPS 1e-8f

// ---------------- scratch (no allocations allowed) ----------------
__device__ float g_rn2_is[BC];     // per-row squared norms of children_is
__device__ float g_rn2_js[BC];     // per-row squared norms of children_js
__device__ float g_sims[B][2 * B]; // [i][0..B) = sim_j, [i][B..2B) = sim_k
__device__ float g_lse[B];         // per-anchor (lse - pos)

// ---------------- kernel 1: per-row squared norms ----------------
// 2*B*C = 4096 rows of 256 floats; one warp per row.
__global__ void rownorm_kernel(const float* __restrict__ is_,
                               const float* __restrict__ js_) {
    int gw   = (blockIdx.x * blockDim.x + threadIdx.x) >> 5;
    int lane = threadIdx.x & 31;
    if (gw >= 2 * BC) return;
    int r = gw & (BC - 1);
    const float* base = (gw < BC) ? is_ : js_;
    const float4* row = (const float4*)(base + (size_t)r * D);
    float4 v0 = row[lane];
    float4 v1 = row[lane + 32];
    float s = v0.x * v0.x + v0.y * v0.y + v0.z * v0.z + v0.w * v0.w
            + v1.x * v1.x + v1.y * v1.y + v1.z * v1.z + v1.w * v1.w;
#pragma unroll
    for (int o = 16; o; o >>= 1) s += __shfl_xor_sync(0xffffffffu, s, o);
    if (lane == 0) {
        float* dst = (gw < BC) ? g_rn2_is : g_rn2_js;
        dst[r] = s;
    }
}

// ---------------- kernel 2: gathered negative similarities ----------------
// grid = dim3(8, B): blockIdx.y = anchor i, blockIdx.x = jb-group of 8.
// 256 threads, warp w handles jb = part*8 + w for BOTH matrices (j then k).
__global__ void sims_kernel(const float* __restrict__ is_,
                            const float* __restrict__ js_,
                            const int* __restrict__ idxj,
                            const int* __restrict__ idxk) {
    __shared__ float s_anchor[F];   // 32 KB: flat_i[i]
    __shared__ float s_na;
    int i    = blockIdx.y;
    int part = blockIdx.x;
    int tid  = threadIdx.x, lane = tid & 31, w = tid >> 5;

    const float4* src = (const float4*)(is_ + (size_t)i * F);
    float4* dst4 = (float4*)s_anchor;
    for (int t = tid; t < F / 4; t += 256) dst4[t] = src[t];
    if (tid < 32) {
        // warp-parallel anchor norm
        float v = g_rn2_is[i * C + tid];
#pragma unroll
        for (int o = 16; o; o >>= 1) v += __shfl_xor_sync(0xffffffffu, v, o);
        if (tid == 0) s_na = sqrtf(v);
    }
    __syncthreads();
    float na = s_na;
    int  jb  = part * 8 + w;

#pragma unroll
    for (int m = 0; m < 2; m++) {
        float sim;
        if (jb == i) {
            sim = -INFINITY;
        } else {
            const float* basev = (m == 0) ? js_ : is_;
            const float* rn2   = (m == 0) ? g_rn2_js : g_rn2_is;
            const int*   idx   = ((m == 0) ? idxj : idxk) + ((size_t)i * B + jb) * C;
            // one coalesced index load per lane; broadcast via shfl in the loop
            int   myidx = idx[lane];
            float n2l   = rn2[jb * C + myidx];   // lane-parallel norm gather
            float acc0 = 0.f, acc1 = 0.f, acc2 = 0.f, acc3 = 0.f;
            float acc4 = 0.f, acc5 = 0.f, acc6 = 0.f, acc7 = 0.f;
#pragma unroll 8
            for (int c = 0; c < C; c++) {
                int r = __shfl_sync(0xffffffffu, myidx, c);
                const float4* row = (const float4*)(basev + ((size_t)(jb * C + r)) * D);
                const float4* anc = (const float4*)(s_anchor + c * D);
                float4 b0 = row[lane];
                float4 b1 = row[lane + 32];
                float4 a0 = anc[lane];
                float4 a1 = anc[lane + 32];
                acc0 += a0.x * b0.x; acc1 += a0.y * b0.y;
                acc2 += a0.z * b0.z; acc3 += a0.w * b0.w;
                acc4 += a1.x * b1.x; acc5 += a1.y * b1.y;
                acc6 += a1.z * b1.z; acc7 += a1.w * b1.w;
            }
            float dot = ((acc0 + acc1) + (acc2 + acc3))
                      + ((acc4 + acc5) + (acc6 + acc7));
#pragma unroll
            for (int o = 16; o; o >>= 1) {
                dot += __shfl_xor_sync(0xffffffffu, dot, o);
                n2l += __shfl_xor_sync(0xffffffffu, n2l, o);
            }
            sim = dot / fmaxf(na * sqrtf(n2l), EPS) / TEMP;
        }
        if (lane == 0) g_sims[i][m * B + jb] = sim;
    }
}

// ---------------- kernel 3: per-anchor positive + logsumexp ----------------
// grid = B blocks, 128 threads. Block i: computes pos_i (8192-dot) and the
// LSE over [pos_i, 128 sims]; writes lse - pos.
__global__ void lse_kernel(const float* __restrict__ is_,
                           const float* __restrict__ js_) {
    __shared__ float sred[4];
    __shared__ float s_bcast;
    int i = blockIdx.x, tid = threadIdx.x, lane = tid & 31, w = tid >> 5;

    // --- pos dot over 8192 ---
    const float4* a  = (const float4*)(is_ + (size_t)i * F);
    const float4* b4 = (const float4*)(js_ + (size_t)i * F);
    float d = 0.f;
#pragma unroll
    for (int t = tid; t < F / 4; t += 128) {
        float4 x = a[t], y = b4[t];
        d += x.x * y.x + x.y * y.y + x.z * y.z + x.w * y.w;
    }
#pragma unroll
    for (int o = 16; o; o >>= 1) d += __shfl_xor_sync(0xffffffffu, d, o);
    if (lane == 0) sred[w] = d;

    // --- anchor norms (warp 0, lane-parallel) ---
    float na2 = 0.f, nb2 = 0.f;
    if (w == 0) {
        na2 = g_rn2_is[i * C + lane];
        nb2 = g_rn2_js[i * C + lane];
#pragma unroll
        for (int o = 16; o; o >>= 1) {
            na2 += __shfl_xor_sync(0xffffffffu, na2, o);
            nb2 += __shfl_xor_sync(0xffffffffu, nb2, o);
        }
    }
    __syncthreads();
    if (tid == 0) {
        float dot = sred[0] + sred[1] + sred[2] + sred[3];
        s_bcast = dot / fmaxf(sqrtf(na2) * sqrtf(nb2), EPS) / TEMP;
    }
    __syncthreads();
    float pos = s_bcast;

    // --- logsumexp over [pos, sims(128)] ---
    float my = g_sims[i][tid];               // one load per thread
    float mx = fmaxf(my, pos);
#pragma unroll
    for (int o = 16; o; o >>= 1) mx = fmaxf(mx, __shfl_xor_sync(0xffffffffu, mx, o));
    if (lane == 0) sred[w] = mx;
    __syncthreads();
    mx = fmaxf(fmaxf(sred[0], sred[1]), fmaxf(sred[2], sred[3]));

    float e = expf(my - mx);                 // exp(-inf - mx) == 0 on diagonal
    if (tid == 0) e += expf(pos - mx);
#pragma unroll
    for (int o = 16; o; o >>= 1) e += __shfl_xor_sync(0xffffffffu, e, o);
    __syncthreads();                         // sred reuse
    if (lane == 0) sred[w] = e;
    __syncthreads();
    if (tid == 0) {
        float s = sred[0] + sred[1] + sred[2] + sred[3];
        g_lse[i] = logf(s) + mx - pos;
    }
}

// ---------------- kernel 4: final sum ----------------
__global__ void final_kernel(float* __restrict__ out) {
    int lane = threadIdx.x;                  // 64 threads, 2 warps
    float v = g_lse[lane];
#pragma unroll
    for (int o = 16; o; o >>= 1) v += __shfl_xor_sync(0xffffffffu, v, o);
    __shared__ float s2[2];
    if ((lane & 31) == 0) s2[lane >> 5] = v;
    __syncthreads();
    if (lane == 0) out[0] = (s2[0] + s2[1]) / (2.0f * B);
}

// ---------------- launch ----------------
extern "C" void kernel_launch(void* const* d_in, const int* in_sizes, int n_in,
                              void* d_out, int out_size) {
    const float* is_  = (const float*)d_in[0];   // children_is [B,C,D] f32
    const float* js_  = (const float*)d_in[1];   // children_js [B,C,D] f32
    const int*   idxj = (const int*)d_in[2];     // neg_idx_j  [B,B,C] i32
    const int*   idxk = (const int*)d_in[3];     // neg_idx_k  [B,B,C] i32
    float* out = (float*)d_out;

    rownorm_kernel<<<(2 * BC) / 8, 256>>>(is_, js_);   // 512 blocks, 1 warp/row
    sims_kernel<<<dim3(8, B), 256>>>(is_, js_, idxj, idxk);
    lse_kernel<<<B, 128>>>(is_, js_);
    final_kernel<<<1, 64>>>(out);
}

// round 6
// speedup vs baseline: 1.6422x; 1.1405x over previous
#include <cuda_runtime.h>
#include <cuda_bf16.h>
#include <math.h>

#define B 64
#define C 32
#define D 256
#define F (C * D)          // 8192
#define BC (B * C)         // 2048
#define TEMP 0.1f
#define EPS 1e-8f

// ---------------- scratch (no allocations allowed) ----------------
__device__ __nv_bfloat16 g_is_bf[BC * D];   // bf16 copy of children_is (1 MB)
__device__ __nv_bfloat16 g_js_bf[BC * D];   // bf16 copy of children_js (1 MB)
__device__ float g_rn2_is[BC];              // per-row squared norms (fp32)
__device__ float g_rn2_js[BC];
__device__ float g_sims[B][2 * B];          // [i][0..B)=sim_j, [B..2B)=sim_k
__device__ float g_lse[B];                  // per-anchor (lse - pos)
__device__ unsigned g_done = 0;             // arrival counter for fused final

__device__ __forceinline__ float2 bf2f(unsigned u) {
    __nv_bfloat162 h = *reinterpret_cast<__nv_bfloat162*>(&u);
    return __bfloat1622float2(h);
}

// ---------------- kernel 1: f32 -> bf16 conversion + per-row norms ----------------
// 2*BC = 4096 rows; one warp per row. Norms computed in fp32 from originals.
__global__ void prep_kernel(const float* __restrict__ is_,
                            const float* __restrict__ js_) {
    int gw   = (blockIdx.x * blockDim.x + threadIdx.x) >> 5;
    int lane = threadIdx.x & 31;
    if (gw >= 2 * BC) return;
    int r = gw & (BC - 1);
    const float* base = (gw < BC) ? is_ : js_;
    __nv_bfloat16* dstb = (gw < BC) ? g_is_bf : g_js_bf;
    const float4* row = (const float4*)(base + (size_t)r * D);
    float4 v0 = row[lane];         // elems 4*lane   .. +3
    float4 v1 = row[lane + 32];    // elems 128+4*lane .. +3
    // fp32 norms
    float s = v0.x * v0.x + v0.y * v0.y + v0.z * v0.z + v0.w * v0.w
            + v1.x * v1.x + v1.y * v1.y + v1.z * v1.z + v1.w * v1.w;
#pragma unroll
    for (int o = 16; o; o >>= 1) s += __shfl_xor_sync(0xffffffffu, s, o);
    if (lane == 0) {
        float* dst = (gw < BC) ? g_rn2_is : g_rn2_js;
        dst[r] = s;
    }
    // bf16 pack (memory element order preserved: .x = lower address)
    __nv_bfloat162 p0 = __floats2bfloat162_rn(v0.x, v0.y);
    __nv_bfloat162 p1 = __floats2bfloat162_rn(v0.z, v0.w);
    __nv_bfloat162 p2 = __floats2bfloat162_rn(v1.x, v1.y);
    __nv_bfloat162 p3 = __floats2bfloat162_rn(v1.z, v1.w);
    char* rowb = (char*)(dstb + (size_t)r * D);
    uint2 w0 = make_uint2(*(unsigned*)&p0, *(unsigned*)&p1);
    uint2 w1 = make_uint2(*(unsigned*)&p2, *(unsigned*)&p3);
    *(uint2*)(rowb + 8 * lane)       = w0;   // bytes of elems 4*lane..
    *(uint2*)(rowb + 256 + 8 * lane) = w1;   // bytes of elems 128+4*lane..
}

// ---------------- kernel 2: gathered negative similarities (bf16 data) ----------------
// grid = dim3(8, B): blockIdx.y = anchor i, blockIdx.x = jb-group of 8.
// 256 threads; warp w handles jb = part*8 + w for both matrices.
__global__ void sims_kernel(const int* __restrict__ idxj,
                            const int* __restrict__ idxk) {
    __shared__ __nv_bfloat16 s_anchor[F];   // 16 KB: bf16 flat_i[i]
    __shared__ float s_na;
    int i    = blockIdx.y;
    int part = blockIdx.x;
    int tid  = threadIdx.x, lane = tid & 31, w = tid >> 5;

    // stage bf16 anchor (16 KB)
    {
        const uint4* src = (const uint4*)(g_is_bf + (size_t)i * F);
        uint4* dst = (uint4*)s_anchor;
        for (int t = tid; t < F / 8; t += 256) dst[t] = src[t];
    }
    if (tid < 32) {
        float v = g_rn2_is[i * C + tid];
#pragma unroll
        for (int o = 16; o; o >>= 1) v += __shfl_xor_sync(0xffffffffu, v, o);
        if (tid == 0) s_na = sqrtf(v);
    }
    __syncthreads();
    float na = s_na;
    int  jb  = part * 8 + w;

#pragma unroll
    for (int m = 0; m < 2; m++) {
        float sim;
        if (jb == i) {
            sim = -INFINITY;
        } else {
            const __nv_bfloat16* basev = (m == 0) ? g_js_bf : g_is_bf;
            const float* rn2 = (m == 0) ? g_rn2_js : g_rn2_is;
            const int*   idx = ((m == 0) ? idxj : idxk) + ((size_t)i * B + jb) * C;
            int   myidx = idx[lane];                 // coalesced, then shfl-broadcast
            float n2l   = rn2[jb * C + myidx];       // lane-parallel norm gather
            float acc0 = 0.f, acc1 = 0.f, acc2 = 0.f, acc3 = 0.f;
            float acc4 = 0.f, acc5 = 0.f, acc6 = 0.f, acc7 = 0.f;
#pragma unroll 8
            for (int c = 0; c < C; c++) {
                int r = __shfl_sync(0xffffffffu, myidx, c);
                // one LDG.128 per lane covers the whole 512B row
                const uint4* row = (const uint4*)(basev + ((size_t)(jb * C + r)) * D);
                const uint4* anc = (const uint4*)(s_anchor + c * D);
                uint4 bv = row[lane];
                uint4 av = anc[lane];
                float2 a0 = bf2f(av.x), b0 = bf2f(bv.x);
                float2 a1 = bf2f(av.y), b1 = bf2f(bv.y);
                float2 a2 = bf2f(av.z), b2 = bf2f(bv.z);
                float2 a3 = bf2f(av.w), b3 = bf2f(bv.w);
                acc0 += a0.x * b0.x; acc1 += a0.y * b0.y;
                acc2 += a1.x * b1.x; acc3 += a1.y * b1.y;
                acc4 += a2.x * b2.x; acc5 += a2.y * b2.y;
                acc6 += a3.x * b3.x; acc7 += a3.y * b3.y;
            }
            float dot = ((acc0 + acc1) + (acc2 + acc3))
                      + ((acc4 + acc5) + (acc6 + acc7));
#pragma unroll
            for (int o = 16; o; o >>= 1) {
                dot += __shfl_xor_sync(0xffffffffu, dot, o);
                n2l += __shfl_xor_sync(0xffffffffu, n2l, o);
            }
            sim = dot / fmaxf(na * sqrtf(n2l), EPS) / TEMP;
        }
        if (lane == 0) g_sims[i][m * B + jb] = sim;
    }
}

// ---------------- kernel 3: positive (fp32) + logsumexp + fused final ----------------
// grid = B blocks, 128 threads. Block i computes pos_i and its LSE; the last
// block to finish deterministically sums all 64 results and writes the loss.
__global__ void lse_kernel(const float* __restrict__ is_,
                           const float* __restrict__ js_,
                           float* __restrict__ out) {
    __shared__ float sred[4];
    __shared__ float s_bcast;
    __shared__ unsigned s_arrived;
    int i = blockIdx.x, tid = threadIdx.x, lane = tid & 31, w = tid >> 5;

    // --- pos dot over 8192 (fp32 originals) ---
    const float4* a  = (const float4*)(is_ + (size_t)i * F);
    const float4* b4 = (const float4*)(js_ + (size_t)i * F);
    float d = 0.f;
#pragma unroll
    for (int t = tid; t < F / 4; t += 128) {
        float4 x = a[t], y = b4[t];
        d += x.x * y.x + x.y * y.y + x.z * y.z + x.w * y.w;
    }
#pragma unroll
    for (int o = 16; o; o >>= 1) d += __shfl_xor_sync(0xffffffffu, d, o);
    if (lane == 0) sred[w] = d;

    // --- anchor norms (warp 0, lane-parallel, fp32) ---
    float na2 = 0.f, nb2 = 0.f;
    if (w == 0) {
        na2 = g_rn2_is[i * C + lane];
        nb2 = g_rn2_js[i * C + lane];
#pragma unroll
        for (int o = 16; o; o >>= 1) {
            na2 += __shfl_xor_sync(0xffffffffu, na2, o);
            nb2 += __shfl_xor_sync(0xffffffffu, nb2, o);
        }
    }
    __syncthreads();
    if (tid == 0) {
        float dot = sred[0] + sred[1] + sred[2] + sred[3];
        s_bcast = dot / fmaxf(sqrtf(na2) * sqrtf(nb2), EPS) / TEMP;
    }
    __syncthreads();
    float pos = s_bcast;

    // --- logsumexp over [pos, sims(128)] ---
    float my = g_sims[i][tid];
    float mx = fmaxf(my, pos);
#pragma unroll
    for (int o = 16; o; o >>= 1) mx = fmaxf(mx, __shfl_xor_sync(0xffffffffu, mx, o));
    if (lane == 0) sred[w] = mx;
    __syncthreads();
    mx = fmaxf(fmaxf(sred[0], sred[1]), fmaxf(sred[2], sred[3]));

    float e = expf(my - mx);                 // exp(-inf - mx) == 0 on diagonal
    if (tid == 0) e += expf(pos - mx);
#pragma unroll
    for (int o = 16; o; o >>= 1) e += __shfl_xor_sync(0xffffffffu, e, o);
    __syncthreads();
    if (lane == 0) sred[w] = e;
    __syncthreads();
    if (tid == 0) {
        float s = sred[0] + sred[1] + sred[2] + sred[3];
        g_lse[i] = logf(s) + mx - pos;
        __threadfence();
        s_arrived = atomicAdd(&g_done, 1u);   // old value
    }
    __syncthreads();

    // --- fused final sum: last block reduces all 64 entries deterministically ---
    if (s_arrived == B - 1) {
        __threadfence();
        if (w == 0) {
            float v = g_lse[lane] + g_lse[lane + 32];
#pragma unroll
            for (int o = 16; o; o >>= 1) v += __shfl_xor_sync(0xffffffffu, v, o);
            if (lane == 0) {
                out[0] = v / (2.0f * B);
                atomicExch(&g_done, 0u);      // reset for next graph replay
            }
        }
    }
}

// ---------------- launch ----------------
extern "C" void kernel_launch(void* const* d_in, const int* in_sizes, int n_in,
                              void* d_out, int out_size) {
    const float* is_  = (const float*)d_in[0];   // children_is [B,C,D] f32
    const float* js_  = (const float*)d_in[1];   // children_js [B,C,D] f32
    const int*   idxj = (const int*)d_in[2];     // neg_idx_j  [B,B,C] i32
    const int*   idxk = (const int*)d_in[3];     // neg_idx_k  [B,B,C] i32
    float* out = (float*)d_out;

    prep_kernel<<<(2 * BC) / 8, 256>>>(is_, js_);     // 512 blocks, 1 warp/row
    sims_kernel<<<dim3(8, B), 256>>>(idxj, idxk);
    lse_kernel<<<B, 128>>>(is_, js_, out);
}

// round 7
// speedup vs baseline: 2.0549x; 1.2514x over previous
#include <cuda_runtime.h>
#include <cuda_bf16.h>
#include <cuda_fp16.h>
#include <cuda_fp8.h>
#include <math.h>

#define B 64
#define C 32
#define D 256
#define F (C * D)          // 8192
#define BC (B * C)         // 2048
#define TEMP 0.1f
#define EPS 1e-8f

// ---------------- scratch (no allocations allowed) ----------------
__device__ __nv_bfloat16 g_is_bf[BC * D];   // bf16 anchors (1 MB)
__device__ unsigned char g_is_f8[BC * D];   // fp8 e4m3 negatives (512 KB)
__device__ unsigned char g_js_f8[BC * D];   // fp8 e4m3 negatives (512 KB)
__device__ float g_rn2_is[BC];              // per-row squared norms (fp32)
__device__ float g_rn2_js[BC];
__device__ float g_pd[BC];                  // per-row positive partial dots (fp32)
__device__ float g_sims[B][2 * B];          // [i][0..B)=sim_j, [B..2B)=sim_k
__device__ float g_lse[B];                  // per-anchor (lse - pos)
__device__ unsigned g_done = 0;             // arrival counter for fused final

__device__ __forceinline__ unsigned pack_f8(float4 v) {
    __nv_fp8x2_storage_t lo = __nv_cvt_float2_to_fp8x2(
        make_float2(v.x, v.y), __NV_SATFINITE, __NV_E4M3);
    __nv_fp8x2_storage_t hi = __nv_cvt_float2_to_fp8x2(
        make_float2(v.z, v.w), __NV_SATFINITE, __NV_E4M3);
    return (unsigned)lo | ((unsigned)hi << 16);
}

__device__ __forceinline__ __half2 f8_to_h2(unsigned short s) {
    __half2_raw hr = __nv_cvt_fp8x2_to_halfraw2((__nv_fp8x2_storage_t)s, __NV_E4M3);
    return *reinterpret_cast<__half2*>(&hr);
}

__device__ __forceinline__ unsigned bf2u_to_h2u(unsigned u) {
    __nv_bfloat162 h = *reinterpret_cast<__nv_bfloat162*>(&u);
    float2 f = __bfloat1622float2(h);
    __half2 r = __float22half2_rn(f);
    return *reinterpret_cast<unsigned*>(&r);
}

// ---------------- kernel 1: prep ----------------
// One warp per row r (2048 rows): loads is/js row pair (fp32), computes both
// norms + the positive partial dot (all fp32), stores bf16 is + fp8 is/js.
__global__ void prep_kernel(const float* __restrict__ is_,
                            const float* __restrict__ js_) {
    int r    = (blockIdx.x * blockDim.x + threadIdx.x) >> 5;   // 0..2047
    int lane = threadIdx.x & 31;
    const float4* ra = (const float4*)(is_ + (size_t)r * D);
    const float4* rb = (const float4*)(js_ + (size_t)r * D);
    float4 a0 = ra[lane], a1 = ra[lane + 32];
    float4 b0 = rb[lane], b1 = rb[lane + 32];

    float sa = a0.x*a0.x + a0.y*a0.y + a0.z*a0.z + a0.w*a0.w
             + a1.x*a1.x + a1.y*a1.y + a1.z*a1.z + a1.w*a1.w;
    float sb = b0.x*b0.x + b0.y*b0.y + b0.z*b0.z + b0.w*b0.w
             + b1.x*b1.x + b1.y*b1.y + b1.z*b1.z + b1.w*b1.w;
    float pd = a0.x*b0.x + a0.y*b0.y + a0.z*b0.z + a0.w*b0.w
             + a1.x*b1.x + a1.y*b1.y + a1.z*b1.z + a1.w*b1.w;
#pragma unroll
    for (int o = 16; o; o >>= 1) {
        sa += __shfl_xor_sync(0xffffffffu, sa, o);
        sb += __shfl_xor_sync(0xffffffffu, sb, o);
        pd += __shfl_xor_sync(0xffffffffu, pd, o);
    }
    if (lane == 0) {
        g_rn2_is[r] = sa;
        g_rn2_js[r] = sb;
        g_pd[r]     = pd;
    }

    // bf16 is (anchor source)
    __nv_bfloat162 p0 = __floats2bfloat162_rn(a0.x, a0.y);
    __nv_bfloat162 p1 = __floats2bfloat162_rn(a0.z, a0.w);
    __nv_bfloat162 p2 = __floats2bfloat162_rn(a1.x, a1.y);
    __nv_bfloat162 p3 = __floats2bfloat162_rn(a1.z, a1.w);
    char* rowb = (char*)(g_is_bf + (size_t)r * D);
    *(uint2*)(rowb + 8 * lane)       = make_uint2(*(unsigned*)&p0, *(unsigned*)&p1);
    *(uint2*)(rowb + 256 + 8 * lane) = make_uint2(*(unsigned*)&p2, *(unsigned*)&p3);

    // fp8 is + js (negative sources)
    unsigned char* rf8a = g_is_f8 + (size_t)r * D;
    unsigned char* rf8b = g_js_f8 + (size_t)r * D;
    *(unsigned*)(rf8a + 4 * lane)       = pack_f8(a0);
    *(unsigned*)(rf8a + 128 + 4 * lane) = pack_f8(a1);
    *(unsigned*)(rf8b + 4 * lane)       = pack_f8(b0);
    *(unsigned*)(rf8b + 128 + 4 * lane) = pack_f8(b1);
}

// ---------------- kernel 2: gathered negative similarities ----------------
// grid = dim3(8, B): blockIdx.y = anchor i, blockIdx.x = jb-group of 8.
// Anchor staged as f16 in smem; negatives fp8 -> f16 hardware cvt; dot via
// HFMA2 with f32 flush every 8 c's.
__global__ void sims_kernel(const int* __restrict__ idxj,
                            const int* __restrict__ idxk) {
    __shared__ __half s_anchor[F];   // 16 KB f16 flat_i[i]
    __shared__ float s_na;
    int i    = blockIdx.y;
    int part = blockIdx.x;
    int tid  = threadIdx.x, lane = tid & 31, w = tid >> 5;

    // stage anchor: bf16 -> f16
    {
        const uint4* src = (const uint4*)(g_is_bf + (size_t)i * F);
        uint4* dst = (uint4*)s_anchor;
        for (int t = tid; t < F / 8; t += 256) {
            uint4 v = src[t];
            uint4 o;
            o.x = bf2u_to_h2u(v.x);
            o.y = bf2u_to_h2u(v.y);
            o.z = bf2u_to_h2u(v.z);
            o.w = bf2u_to_h2u(v.w);
            dst[t] = o;
        }
    }
    if (tid < 32) {
        float v = g_rn2_is[i * C + tid];
#pragma unroll
        for (int o = 16; o; o >>= 1) v += __shfl_xor_sync(0xffffffffu, v, o);
        if (tid == 0) s_na = sqrtf(v);
    }
    __syncthreads();
    float na = s_na;
    int  jb  = part * 8 + w;

#pragma unroll
    for (int m = 0; m < 2; m++) {
        float sim;
        if (jb == i) {
            sim = -INFINITY;
        } else {
            const unsigned char* basev = (m == 0) ? g_js_f8 : g_is_f8;
            const float* rn2 = (m == 0) ? g_rn2_js : g_rn2_is;
            const int*   idx = ((m == 0) ? idxj : idxk) + ((size_t)i * B + jb) * C;
            int   myidx = idx[lane];                 // coalesced, shfl-broadcast
            float n2l   = rn2[jb * C + myidx];       // lane-parallel norm gather
            float fa0 = 0.f, fa1 = 0.f, fa2 = 0.f, fa3 = 0.f;
            float fa4 = 0.f, fa5 = 0.f, fa6 = 0.f, fa7 = 0.f;
#pragma unroll
            for (int cb = 0; cb < 4; cb++) {
                __half2 h0 = __float2half2_rn(0.f);
                __half2 h1 = __float2half2_rn(0.f);
                __half2 h2 = __float2half2_rn(0.f);
                __half2 h3 = __float2half2_rn(0.f);
#pragma unroll
                for (int cc = 0; cc < 8; cc++) {
                    int c = cb * 8 + cc;
                    int rr = __shfl_sync(0xffffffffu, myidx, c);
                    const uint2* row = (const uint2*)(basev + ((size_t)(jb * C + rr)) * D);
                    uint2 bv = row[lane];                       // 8 fp8 elems
                    const uint4* anc = (const uint4*)(s_anchor + c * D);
                    uint4 av = anc[lane];                       // 8 f16 elems
                    __half2 b0 = f8_to_h2((unsigned short)(bv.x & 0xffffu));
                    __half2 b1 = f8_to_h2((unsigned short)(bv.x >> 16));
                    __half2 b2 = f8_to_h2((unsigned short)(bv.y & 0xffffu));
                    __half2 b3 = f8_to_h2((unsigned short)(bv.y >> 16));
                    h0 = __hfma2(*reinterpret_cast<__half2*>(&av.x), b0, h0);
                    h1 = __hfma2(*reinterpret_cast<__half2*>(&av.y), b1, h1);
                    h2 = __hfma2(*reinterpret_cast<__half2*>(&av.z), b2, h2);
                    h3 = __hfma2(*reinterpret_cast<__half2*>(&av.w), b3, h3);
                }
                float2 f0 = __half22float2(h0);
                float2 f1 = __half22float2(h1);
                float2 f2 = __half22float2(h2);
                float2 f3 = __half22float2(h3);
                fa0 += f0.x; fa1 += f0.y; fa2 += f1.x; fa3 += f1.y;
                fa4 += f2.x; fa5 += f2.y; fa6 += f3.x; fa7 += f3.y;
            }
            float dot = ((fa0 + fa1) + (fa2 + fa3)) + ((fa4 + fa5) + (fa6 + fa7));
#pragma unroll
            for (int o = 16; o; o >>= 1) {
                dot += __shfl_xor_sync(0xffffffffu, dot, o);
                n2l += __shfl_xor_sync(0xffffffffu, n2l, o);
            }
            sim = dot / fmaxf(na * sqrtf(n2l), EPS) / TEMP;
        }
        if (lane == 0) g_sims[i][m * B + jb] = sim;
    }
}

// ---------------- kernel 3: logsumexp + fused final ----------------
// grid = B blocks, 128 threads. pos_i assembled from g_pd; LSE over 129
// logits; last-arriving block does the deterministic 64-way final sum.
__global__ void lse_kernel(float* __restrict__ out) {
    __shared__ float sred[4];
    __shared__ float s_bcast;
    __shared__ unsigned s_arrived;
    int i = blockIdx.x, tid = threadIdx.x, lane = tid & 31, w = tid >> 5;

    if (w == 0) {
        float pd  = g_pd[i * C + lane];
        float na2 = g_rn2_is[i * C + lane];
        float nb2 = g_rn2_js[i * C + lane];
#pragma unroll
        for (int o = 16; o; o >>= 1) {
            pd  += __shfl_xor_sync(0xffffffffu, pd, o);
            na2 += __shfl_xor_sync(0xffffffffu, na2, o);
            nb2 += __shfl_xor_sync(0xffffffffu, nb2, o);
        }
        if (lane == 0)
            s_bcast = pd / fmaxf(sqrtf(na2) * sqrtf(nb2), EPS) / TEMP;
    }
    __syncthreads();
    float pos = s_bcast;

    float my = g_sims[i][tid];
    float mx = fmaxf(my, pos);
#pragma unroll
    for (int o = 16; o; o >>= 1) mx = fmaxf(mx, __shfl_xor_sync(0xffffffffu, mx, o));
    if (lane == 0) sred[w] = mx;
    __syncthreads();
    mx = fmaxf(fmaxf(sred[0], sred[1]), fmaxf(sred[2], sred[3]));

    float e = expf(my - mx);                 // exp(-inf - mx) == 0 on diagonal
    if (tid == 0) e += expf(pos - mx);
#pragma unroll
    for (int o = 16; o; o >>= 1) e += __shfl_xor_sync(0xffffffffu, e, o);
    __syncthreads();
    if (lane == 0) sred[w] = e;
    __syncthreads();
    if (tid == 0) {
        float s = sred[0] + sred[1] + sred[2] + sred[3];
        g_lse[i] = logf(s) + mx - pos;
        __threadfence();
        s_arrived = atomicAdd(&g_done, 1u);   // old value
    }
    __syncthreads();

    if (s_arrived == B - 1) {                 // last block finishes the sum
        __threadfence();
        if (w == 0) {
            float v = g_lse[lane] + g_lse[lane + 32];
#pragma unroll
            for (int o = 16; o; o >>= 1) v += __shfl_xor_sync(0xffffffffu, v, o);
            if (lane == 0) {
                out[0] = v / (2.0f * B);
                atomicExch(&g_done, 0u);      // reset for next graph replay
            }
        }
    }
}

// ---------------- launch ----------------
extern "C" void kernel_launch(void* const* d_in, const int* in_sizes, int n_in,
                              void* d_out, int out_size) {
    const float* is_  = (const float*)d_in[0];   // children_is [B,C,D] f32
    const float* js_  = (const float*)d_in[1];   // children_js [B,C,D] f32
    const int*   idxj = (const int*)d_in[2];     // neg_idx_j  [B,B,C] i32
    const int*   idxk = (const int*)d_in[3];     // neg_idx_k  [B,B,C] i32
    float* out = (float*)d_out;

    prep_kernel<<<BC / 8, 256>>>(is_, js_);          // 256 CTAs, 1 warp/row-pair
    sims_kernel<<<dim3(8, B), 256>>>(idxj, idxk);
    lse_kernel<<<B, 128>>>(out);
}

// round 8
// speedup vs baseline: 2.2840x; 1.1115x over previous
#include <cuda_runtime.h>
#include <cuda_fp16.h>
#include <cuda_fp8.h>
#include <math.h>

#define B 64
#define C 32
#define D 256
#define F (C * D)          // 8192
#define BC (B * C)         // 2048
#define TEMP 0.1f
#define EPS 1e-8f

// ---------------- scratch (no allocations allowed) ----------------
__device__ __half g_is_h[BC * D];           // f16 anchors (1 MB)
__device__ unsigned char g_is_f8[BC * D];   // fp8 e4m3 negatives (512 KB)
__device__ unsigned char g_js_f8[BC * D];   // fp8 e4m3 negatives (512 KB)
__device__ float g_rn2_is[BC];              // per-row squared norms (fp32)
__device__ float g_rn2_js[BC];
__device__ float g_pd[BC];                  // per-row positive partial dots (fp32)
__device__ float g_sims[B][2 * B];          // [i][0..B)=sim_j, [B..2B)=sim_k
__device__ float g_lse[B];                  // per-anchor (lse - pos)
__device__ unsigned g_done = 0;             // arrival counter for fused final

__device__ __forceinline__ unsigned pack_f8(float4 v) {
    __nv_fp8x2_storage_t lo = __nv_cvt_float2_to_fp8x2(
        make_float2(v.x, v.y), __NV_SATFINITE, __NV_E4M3);
    __nv_fp8x2_storage_t hi = __nv_cvt_float2_to_fp8x2(
        make_float2(v.z, v.w), __NV_SATFINITE, __NV_E4M3);
    return (unsigned)lo | ((unsigned)hi << 16);
}

__device__ __forceinline__ __half2 f8_to_h2(unsigned short s) {
    __half2_raw hr = __nv_cvt_fp8x2_to_halfraw2((__nv_fp8x2_storage_t)s, __NV_E4M3);
    return *reinterpret_cast<__half2*>(&hr);
}

// ---------------- kernel 1: prep ----------------
// One warp per HALF row (4096 warps): loads 128-elem is/js half-row pair,
// partial norms + positive dot (fp32), stores f16 is + fp8 is/js.
// CTA = 256 threads = 8 warps = 4 rows; halves combined via smem.
__global__ void prep_kernel(const float* __restrict__ is_,
                            const float* __restrict__ js_) {
    __shared__ float s_p[8][3];
    int tid  = threadIdx.x, lane = tid & 31, w = tid >> 5;
    int r    = blockIdx.x * 4 + (w >> 1);     // row 0..2047
    int half = w & 1;                          // which 128-elem half
    int off  = r * D + half * 128 + lane * 4;  // element offset

    float4 a = *(const float4*)(is_ + off);
    float4 b = *(const float4*)(js_ + off);

    float sa = a.x*a.x + a.y*a.y + a.z*a.z + a.w*a.w;
    float sb = b.x*b.x + b.y*b.y + b.z*b.z + b.w*b.w;
    float pd = a.x*b.x + a.y*b.y + a.z*b.z + a.w*b.w;
#pragma unroll
    for (int o = 16; o; o >>= 1) {
        sa += __shfl_xor_sync(0xffffffffu, sa, o);
        sb += __shfl_xor_sync(0xffffffffu, sb, o);
        pd += __shfl_xor_sync(0xffffffffu, pd, o);
    }
    if (lane == 0) { s_p[w][0] = sa; s_p[w][1] = sb; s_p[w][2] = pd; }

    // f16 is (anchor)
    __half2 h0 = __float22half2_rn(make_float2(a.x, a.y));
    __half2 h1 = __float22half2_rn(make_float2(a.z, a.w));
    *(uint2*)(g_is_h + off) = make_uint2(*(unsigned*)&h0, *(unsigned*)&h1);
    // fp8 is + js (negatives)
    *(unsigned*)(g_is_f8 + off) = pack_f8(a);
    *(unsigned*)(g_js_f8 + off) = pack_f8(b);

    __syncthreads();
    if (tid < 4) {
        int rr = blockIdx.x * 4 + tid;
        g_rn2_is[rr] = s_p[2*tid][0] + s_p[2*tid+1][0];
        g_rn2_js[rr] = s_p[2*tid][1] + s_p[2*tid+1][1];
        g_pd[rr]     = s_p[2*tid][2] + s_p[2*tid+1][2];
    }
}

// ---------------- kernel 2: gathered negative similarities ----------------
// grid = dim3(8, B): blockIdx.y = anchor i, blockIdx.x = jb-group of 8.
// Warp w handles jb = part*8 + w, computing sim_j AND sim_k in ONE fused
// loop: anchor LDS.128 read once serves both dots; both gather LDGs in
// flight together (2x MLP).
__global__ void sims_kernel(const int* __restrict__ idxj,
                            const int* __restrict__ idxk) {
    __shared__ __half s_anchor[F];   // 16 KB f16 flat_i[i]
    __shared__ float s_na;
    int i    = blockIdx.y;
    int part = blockIdx.x;
    int tid  = threadIdx.x, lane = tid & 31, w = tid >> 5;

    // stage f16 anchor (16 KB, plain copy)
    {
        const uint4* src = (const uint4*)(g_is_h + (size_t)i * F);
        uint4* dst = (uint4*)s_anchor;
#pragma unroll
        for (int t = 0; t < 4; t++) dst[tid + 256 * t] = src[tid + 256 * t];
    }
    if (tid < 32) {
        float v = g_rn2_is[i * C + tid];
#pragma unroll
        for (int o = 16; o; o >>= 1) v += __shfl_xor_sync(0xffffffffu, v, o);
        if (tid == 0) s_na = sqrtf(v);
    }
    __syncthreads();
    float na = s_na;
    int  jb  = part * 8 + w;

    if (jb == i) {
        if (lane == 0) {
            g_sims[i][jb]     = -INFINITY;
            g_sims[i][B + jb] = -INFINITY;
        }
        return;
    }

    const int* idxJ = idxj + ((size_t)i * B + jb) * C;
    const int* idxK = idxk + ((size_t)i * B + jb) * C;
    int   mj  = idxJ[lane];                    // coalesced, shfl-broadcast
    int   mk  = idxK[lane];
    float n2j = g_rn2_js[jb * C + mj];         // lane-parallel norm gathers
    float n2k = g_rn2_is[jb * C + mk];

    const unsigned char* baseJ = g_js_f8 + (size_t)jb * C * D + 8 * lane;
    const unsigned char* baseK = g_is_f8 + (size_t)jb * C * D + 8 * lane;

    float fj0 = 0.f, fj1 = 0.f, fj2 = 0.f, fj3 = 0.f;
    float fk0 = 0.f, fk1 = 0.f, fk2 = 0.f, fk3 = 0.f;
#pragma unroll
    for (int cb = 0; cb < 4; cb++) {
        __half2 hj0 = __float2half2_rn(0.f), hj1 = hj0, hj2 = hj0, hj3 = hj0;
        __half2 hk0 = hj0, hk1 = hj0, hk2 = hj0, hk3 = hj0;
#pragma unroll
        for (int cc = 0; cc < 8; cc++) {
            int c  = cb * 8 + cc;
            int rj = __shfl_sync(0xffffffffu, mj, c);
            int rk = __shfl_sync(0xffffffffu, mk, c);
            uint2 bvj = *(const uint2*)(baseJ + (size_t)rj * D);   // 8 fp8
            uint2 bvk = *(const uint2*)(baseK + (size_t)rk * D);   // 8 fp8
            uint4 av  = *(const uint4*)(s_anchor + c * D + 8 * lane); // 8 f16
            __half2 a0 = *reinterpret_cast<__half2*>(&av.x);
            __half2 a1 = *reinterpret_cast<__half2*>(&av.y);
            __half2 a2 = *reinterpret_cast<__half2*>(&av.z);
            __half2 a3 = *reinterpret_cast<__half2*>(&av.w);
            hj0 = __hfma2(a0, f8_to_h2((unsigned short)(bvj.x & 0xffffu)), hj0);
            hj1 = __hfma2(a1, f8_to_h2((unsigned short)(bvj.x >> 16)),     hj1);
            hj2 = __hfma2(a2, f8_to_h2((unsigned short)(bvj.y & 0xffffu)), hj2);
            hj3 = __hfma2(a3, f8_to_h2((unsigned short)(bvj.y >> 16)),     hj3);
            hk0 = __hfma2(a0, f8_to_h2((unsigned short)(bvk.x & 0xffffu)), hk0);
            hk1 = __hfma2(a1, f8_to_h2((unsigned short)(bvk.x >> 16)),     hk1);
            hk2 = __hfma2(a2, f8_to_h2((unsigned short)(bvk.y & 0xffffu)), hk2);
            hk3 = __hfma2(a3, f8_to_h2((unsigned short)(bvk.y >> 16)),     hk3);
        }
        float2 t;
        t = __half22float2(hj0); fj0 += t.x + t.y;
        t = __half22float2(hj1); fj1 += t.x + t.y;
        t = __half22float2(hj2); fj2 += t.x + t.y;
        t = __half22float2(hj3); fj3 += t.x + t.y;
        t = __half22float2(hk0); fk0 += t.x + t.y;
        t = __half22float2(hk1); fk1 += t.x + t.y;
        t = __half22float2(hk2); fk2 += t.x + t.y;
        t = __half22float2(hk3); fk3 += t.x + t.y;
    }
    float dj = (fj0 + fj1) + (fj2 + fj3);
    float dk = (fk0 + fk1) + (fk2 + fk3);
#pragma unroll
    for (int o = 16; o; o >>= 1) {
        dj  += __shfl_xor_sync(0xffffffffu, dj, o);
        dk  += __shfl_xor_sync(0xffffffffu, dk, o);
        n2j += __shfl_xor_sync(0xffffffffu, n2j, o);
        n2k += __shfl_xor_sync(0xffffffffu, n2k, o);
    }
    if (lane == 0) {
        g_sims[i][jb]     = dj / fmaxf(na * sqrtf(n2j), EPS) / TEMP;
        g_sims[i][B + jb] = dk / fmaxf(na * sqrtf(n2k), EPS) / TEMP;
    }
}

// ---------------- kernel 3: logsumexp + fused final ----------------
__global__ void lse_kernel(float* __restrict__ out) {
    __shared__ float sred[4];
    __shared__ float s_bcast;
    __shared__ unsigned s_arrived;
    int i = blockIdx.x, tid = threadIdx.x, lane = tid & 31, w = tid >> 5;

    if (w == 0) {
        float pd  = g_pd[i * C + lane];
        float na2 = g_rn2_is[i * C + lane];
        float nb2 = g_rn2_js[i * C + lane];
#pragma unroll
        for (int o = 16; o; o >>= 1) {
            pd  += __shfl_xor_sync(0xffffffffu, pd, o);
            na2 += __shfl_xor_sync(0xffffffffu, na2, o);
            nb2 += __shfl_xor_sync(0xffffffffu, nb2, o);
        }
        if (lane == 0)
            s_bcast = pd / fmaxf(sqrtf(na2) * sqrtf(nb2), EPS) / TEMP;
    }
    __syncthreads();
    float pos = s_bcast;

    float my = g_sims[i][tid];
    float mx = fmaxf(my, pos);
#pragma unroll
    for (int o = 16; o; o >>= 1) mx = fmaxf(mx, __shfl_xor_sync(0xffffffffu, mx, o));
    if (lane == 0) sred[w] = mx;
    __syncthreads();
    mx = fmaxf(fmaxf(sred[0], sred[1]), fmaxf(sred[2], sred[3]));

    float e = expf(my - mx);                 // exp(-inf - mx) == 0 on diagonal
    if (tid == 0) e += expf(pos - mx);
#pragma unroll
    for (int o = 16; o; o >>= 1) e += __shfl_xor_sync(0xffffffffu, e, o);
    __syncthreads();
    if (lane == 0) sred[w] = e;
    __syncthreads();
    if (tid == 0) {
        float s = sred[0] + sred[1] + sred[2] + sred[3];
        g_lse[i] = logf(s) + mx - pos;
        __threadfence();
        s_arrived = atomicAdd(&g_done, 1u);   // old value
    }
    __syncthreads();

    if (s_arrived == B - 1) {                 // last block finishes the sum
        __threadfence();
        if (w == 0) {
            float v = g_lse[lane] + g_lse[lane + 32];
#pragma unroll
            for (int o = 16; o; o >>= 1) v += __shfl_xor_sync(0xffffffffu, v, o);
            if (lane == 0) {
                out[0] = v / (2.0f * B);
                atomicExch(&g_done, 0u);      // reset for next graph replay
            }
        }
    }
}

// ---------------- launch ----------------
extern "C" void kernel_launch(void* const* d_in, const int* in_sizes, int n_in,
                              void* d_out, int out_size) {
    const float* is_  = (const float*)d_in[0];   // children_is [B,C,D] f32
    const float* js_  = (const float*)d_in[1];   // children_js [B,C,D] f32
    const int*   idxj = (const int*)d_in[2];     // neg_idx_j  [B,B,C] i32
    const int*   idxk = (const int*)d_in[3];     // neg_idx_k  [B,B,C] i32
    float* out = (float*)d_out;

    prep_kernel<<<BC / 4, 256>>>(is_, js_);       // 512 CTAs, 1 warp/half-row
    sims_kernel<<<dim3(8, B), 256>>>(idxj, idxk);
    lse_kernel<<<B, 128>>>(out);
}

// round 9
// speedup vs baseline: 2.4933x; 1.0917x over previous
#include <cuda_runtime.h>
#include <cuda_fp16.h>
#include <cuda_fp8.h>
#include <math.h>

#define B 64
#define C 32
#define D 256
#define F (C * D)          // 8192
#define BC (B * C)         // 2048
#define TEMP 0.1f
#define EPS 1e-8f

// ---------------- scratch (no allocations allowed) ----------------
__device__ __half g_is_h[BC * D];           // f16 anchors (1 MB)
__device__ unsigned char g_is_f8[BC * D];   // fp8 e4m3 negatives (512 KB)
__device__ unsigned char g_js_f8[BC * D];   // fp8 e4m3 negatives (512 KB)
__device__ float g_rn2_is[BC];              // per-row squared norms (fp32)
__device__ float g_rn2_js[BC];
__device__ float g_pd[BC];                  // per-row positive partial dots (fp32)
__device__ float g_sims[B][2 * B];          // [i][0..B)=sim_j, [B..2B)=sim_k
__device__ float g_lse[B];                  // per-anchor (lse - pos)
__device__ unsigned g_done = 0;             // arrival counter for fused final

__device__ __forceinline__ unsigned pack_f8(float4 v) {
    __nv_fp8x2_storage_t lo = __nv_cvt_float2_to_fp8x2(
        make_float2(v.x, v.y), __NV_SATFINITE, __NV_E4M3);
    __nv_fp8x2_storage_t hi = __nv_cvt_float2_to_fp8x2(
        make_float2(v.z, v.w), __NV_SATFINITE, __NV_E4M3);
    return (unsigned)lo | ((unsigned)hi << 16);
}

__device__ __forceinline__ __half2 f8_to_h2(unsigned short s) {
    __half2_raw hr = __nv_cvt_fp8x2_to_halfraw2((__nv_fp8x2_storage_t)s, __NV_E4M3);
    return *reinterpret_cast<__half2*>(&hr);
}

// ---------------- kernel 1: prep ----------------
// One warp per HALF row (4096 warps): loads 128-elem is/js half-row pair,
// partial norms + positive dot (fp32), stores f16 is + fp8 is/js.
__global__ void prep_kernel(const float* __restrict__ is_,
                            const float* __restrict__ js_) {
    __shared__ float s_p[8][3];
    int tid  = threadIdx.x, lane = tid & 31, w = tid >> 5;
    int r    = blockIdx.x * 4 + (w >> 1);     // row 0..2047
    int half = w & 1;                          // which 128-elem half
    int off  = r * D + half * 128 + lane * 4;  // element offset

    float4 a = *(const float4*)(is_ + off);
    float4 b = *(const float4*)(js_ + off);

    float sa = a.x*a.x + a.y*a.y + a.z*a.z + a.w*a.w;
    float sb = b.x*b.x + b.y*b.y + b.z*b.z + b.w*b.w;
    float pd = a.x*b.x + a.y*b.y + a.z*b.z + a.w*b.w;
#pragma unroll
    for (int o = 16; o; o >>= 1) {
        sa += __shfl_xor_sync(0xffffffffu, sa, o);
        sb += __shfl_xor_sync(0xffffffffu, sb, o);
        pd += __shfl_xor_sync(0xffffffffu, pd, o);
    }
    if (lane == 0) { s_p[w][0] = sa; s_p[w][1] = sb; s_p[w][2] = pd; }

    __half2 h0 = __float22half2_rn(make_float2(a.x, a.y));
    __half2 h1 = __float22half2_rn(make_float2(a.z, a.w));
    *(uint2*)(g_is_h + off) = make_uint2(*(unsigned*)&h0, *(unsigned*)&h1);
    *(unsigned*)(g_is_f8 + off) = pack_f8(a);
    *(unsigned*)(g_js_f8 + off) = pack_f8(b);

    __syncthreads();
    if (tid < 4) {
        int rr = blockIdx.x * 4 + tid;
        g_rn2_is[rr] = s_p[2*tid][0] + s_p[2*tid+1][0];
        g_rn2_js[rr] = s_p[2*tid][1] + s_p[2*tid+1][1];
        g_pd[rr]     = s_p[2*tid][2] + s_p[2*tid+1][2];
    }
}

// ---------------- kernel 2: gathered negative similarities ----------------
// grid = dim3(16, B): blockIdx.y = anchor i, blockIdx.x = group of 4 jb.
// TWO warps per (i, jb) task: warp pair (task, half) each covers 16 c's,
// computing sim_j AND sim_k fused. Partials combined in smem.
__global__ void sims_kernel(const int* __restrict__ idxj,
                            const int* __restrict__ idxk) {
    __shared__ __half s_anchor[F];   // 16 KB f16 flat_i[i]
    __shared__ float s_na;
    __shared__ float s_dj[8], s_dk[8], s_n2j[4], s_n2k[4];
    int i    = blockIdx.y;
    int part = blockIdx.x;           // 0..15
    int tid  = threadIdx.x, lane = tid & 31, w = tid >> 5;
    int task = w >> 1;               // 0..3 -> jb = part*4 + task
    int half = w & 1;                // which 16 c's
    int jb   = part * 4 + task;

    // stage f16 anchor (16 KB)
    {
        const uint4* src = (const uint4*)(g_is_h + (size_t)i * F);
        uint4* dst = (uint4*)s_anchor;
#pragma unroll
        for (int t = 0; t < 4; t++) dst[tid + 256 * t] = src[tid + 256 * t];
    }
    if (tid < 32) {
        float v = g_rn2_is[i * C + tid];
#pragma unroll
        for (int o = 16; o; o >>= 1) v += __shfl_xor_sync(0xffffffffu, v, o);
        if (tid == 0) s_na = sqrtf(v);
    }

    if (jb != i) {
        const int* idxJ = idxj + ((size_t)i * B + jb) * C;
        const int* idxK = idxk + ((size_t)i * B + jb) * C;
        int mj = idxJ[lane];                 // all 32 indices (shfl source)
        int mk = idxK[lane];
        float n2j = 0.f, n2k = 0.f;
        if (half == 0) {                     // half 0 owns the norm gathers
            n2j = g_rn2_js[jb * C + mj];
            n2k = g_rn2_is[jb * C + mk];
        }
        const unsigned char* baseJ = g_js_f8 + (size_t)jb * C * D + 8 * lane;
        const unsigned char* baseK = g_is_f8 + (size_t)jb * C * D + 8 * lane;

        float fj0 = 0.f, fj1 = 0.f, fj2 = 0.f, fj3 = 0.f;
        float fk0 = 0.f, fk1 = 0.f, fk2 = 0.f, fk3 = 0.f;
#pragma unroll
        for (int cb = 0; cb < 2; cb++) {
            __half2 hj0 = __float2half2_rn(0.f), hj1 = hj0, hj2 = hj0, hj3 = hj0;
            __half2 hk0 = hj0, hk1 = hj0, hk2 = hj0, hk3 = hj0;
#pragma unroll
            for (int cc = 0; cc < 8; cc++) {
                int c  = half * 16 + cb * 8 + cc;
                int rj = __shfl_sync(0xffffffffu, mj, c);
                int rk = __shfl_sync(0xffffffffu, mk, c);
                uint2 bvj = *(const uint2*)(baseJ + (size_t)rj * D);
                uint2 bvk = *(const uint2*)(baseK + (size_t)rk * D);
                uint4 av  = *(const uint4*)(s_anchor + c * D + 8 * lane);
                __half2 a0 = *reinterpret_cast<__half2*>(&av.x);
                __half2 a1 = *reinterpret_cast<__half2*>(&av.y);
                __half2 a2 = *reinterpret_cast<__half2*>(&av.z);
                __half2 a3 = *reinterpret_cast<__half2*>(&av.w);
                hj0 = __hfma2(a0, f8_to_h2((unsigned short)(bvj.x & 0xffffu)), hj0);
                hj1 = __hfma2(a1, f8_to_h2((unsigned short)(bvj.x >> 16)),     hj1);
                hj2 = __hfma2(a2, f8_to_h2((unsigned short)(bvj.y & 0xffffu)), hj2);
                hj3 = __hfma2(a3, f8_to_h2((unsigned short)(bvj.y >> 16)),     hj3);
                hk0 = __hfma2(a0, f8_to_h2((unsigned short)(bvk.x & 0xffffu)), hk0);
                hk1 = __hfma2(a1, f8_to_h2((unsigned short)(bvk.x >> 16)),     hk1);
                hk2 = __hfma2(a2, f8_to_h2((unsigned short)(bvk.y & 0xffffu)), hk2);
                hk3 = __hfma2(a3, f8_to_h2((unsigned short)(bvk.y >> 16)),     hk3);
            }
            float2 t;
            t = __half22float2(hj0); fj0 += t.x + t.y;
            t = __half22float2(hj1); fj1 += t.x + t.y;
            t = __half22float2(hj2); fj2 += t.x + t.y;
            t = __half22float2(hj3); fj3 += t.x + t.y;
            t = __half22float2(hk0); fk0 += t.x + t.y;
            t = __half22float2(hk1); fk1 += t.x + t.y;
            t = __half22float2(hk2); fk2 += t.x + t.y;
            t = __half22float2(hk3); fk3 += t.x + t.y;
        }
        float dj = (fj0 + fj1) + (fj2 + fj3);
        float dk = (fk0 + fk1) + (fk2 + fk3);
#pragma unroll
        for (int o = 16; o; o >>= 1) {
            dj += __shfl_xor_sync(0xffffffffu, dj, o);
            dk += __shfl_xor_sync(0xffffffffu, dk, o);
        }
        if (half == 0) {
#pragma unroll
            for (int o = 16; o; o >>= 1) {
                n2j += __shfl_xor_sync(0xffffffffu, n2j, o);
                n2k += __shfl_xor_sync(0xffffffffu, n2k, o);
            }
            if (lane == 0) { s_n2j[task] = n2j; s_n2k[task] = n2k; }
        }
        if (lane == 0) { s_dj[w] = dj; s_dk[w] = dk; }
    }
    __syncthreads();

    // warps 0..3 finalize task w
    if (w < 4 && lane == 0) {
        int jb2 = part * 4 + w;
        if (jb2 == i) {
            g_sims[i][jb2]     = -INFINITY;
            g_sims[i][B + jb2] = -INFINITY;
        } else {
            float na = s_na;
            float dj = s_dj[2 * w] + s_dj[2 * w + 1];
            float dk = s_dk[2 * w] + s_dk[2 * w + 1];
            g_sims[i][jb2]     = dj / fmaxf(na * sqrtf(s_n2j[w]), EPS) / TEMP;
            g_sims[i][B + jb2] = dk / fmaxf(na * sqrtf(s_n2k[w]), EPS) / TEMP;
        }
    }
}

// ---------------- kernel 3: logsumexp + fused final ----------------
__global__ void lse_kernel(float* __restrict__ out) {
    __shared__ float sred[4];
    __shared__ float s_bcast;
    __shared__ unsigned s_arrived;
    int i = blockIdx.x, tid = threadIdx.x, lane = tid & 31, w = tid >> 5;

    if (w == 0) {
        float pd  = g_pd[i * C + lane];
        float na2 = g_rn2_is[i * C + lane];
        float nb2 = g_rn2_js[i * C + lane];
#pragma unroll
        for (int o = 16; o; o >>= 1) {
            pd  += __shfl_xor_sync(0xffffffffu, pd, o);
            na2 += __shfl_xor_sync(0xffffffffu, na2, o);
            nb2 += __shfl_xor_sync(0xffffffffu, nb2, o);
        }
        if (lane == 0)
            s_bcast = pd / fmaxf(sqrtf(na2) * sqrtf(nb2), EPS) / TEMP;
    }
    __syncthreads();
    float pos = s_bcast;

    float my = g_sims[i][tid];
    float mx = fmaxf(my, pos);
#pragma unroll
    for (int o = 16; o; o >>= 1) mx = fmaxf(mx, __shfl_xor_sync(0xffffffffu, mx, o));
    if (lane == 0) sred[w] = mx;
    __syncthreads();
    mx = fmaxf(fmaxf(sred[0], sred[1]), fmaxf(sred[2], sred[3]));

    float e = expf(my - mx);                 // exp(-inf - mx) == 0 on diagonal
    if (tid == 0) e += expf(pos - mx);
#pragma unroll
    for (int o = 16; o; o >>= 1) e += __shfl_xor_sync(0xffffffffu, e, o);
    __syncthreads();
    if (lane == 0) sred[w] = e;
    __syncthreads();
    if (tid == 0) {
        float s = sred[0] + sred[1] + sred[2] + sred[3];
        g_lse[i] = logf(s) + mx - pos;
        __threadfence();
        s_arrived = atomicAdd(&g_done, 1u);   // old value
    }
    __syncthreads();

    if (s_arrived == B - 1) {                 // last block finishes the sum
        __threadfence();
        if (w == 0) {
            float v = g_lse[lane] + g_lse[lane + 32];
#pragma unroll
            for (int o = 16; o; o >>= 1) v += __shfl_xor_sync(0xffffffffu, v, o);
            if (lane == 0) {
                out[0] = v / (2.0f * B);
                atomicExch(&g_done, 0u);      // reset for next graph replay
            }
        }
    }
}

// ---------------- launch ----------------
extern "C" void kernel_launch(void* const* d_in, const int* in_sizes, int n_in,
                              void* d_out, int out_size) {
    const float* is_  = (const float*)d_in[0];   // children_is [B,C,D] f32
    const float* js_  = (const float*)d_in[1];   // children_js [B,C,D] f32
    const int*   idxj = (const int*)d_in[2];     // neg_idx_j  [B,B,C] i32
    const int*   idxk = (const int*)d_in[3];     // neg_idx_k  [B,B,C] i32
    float* out = (float*)d_out;

    prep_kernel<<<BC / 4, 256>>>(is_, js_);        // 512 CTAs, 1 warp/half-row
    sims_kernel<<<dim3(16, B), 256>>>(idxj, idxk); // 1024 CTAs, 2 warps/task
    lse_kernel<<<B, 128>>>(out);
}